// round 15
// baseline (speedup 1.0000x reference)
#include <cuda_runtime.h>
#include <cuda_bf16.h>
#include <cstdint>

#define NP 2048
#define NC 64
#define CDIM 128
#define DDIM 64
#define NCC (NC*CDIM)              /* 8192 */
#define TOT ((size_t)NP*NCC)       /* 16777216 */
#define P_TOPP 0.9f
#define LN_EPS 1e-5f

typedef __nv_bfloat16 bf16;

// ---------------- scratch (device globals; allowed) ----------------
__device__ __align__(128) bf16  g_RfB[(size_t)NP*NP];
__device__ __align__(128) float g_attn[(size_t)NP*NP];     // raw logits
__device__ __align__(128) bf16  g_attnB[(size_t)NP*NP];    // masked+renormed bf16
__device__ float g_pooled[NP*CDIM];
__device__ float g_e3[NP*DDIM];
__device__ float g_fm[NP*DDIM];
__device__ __align__(128) bf16 g_xT[TOT];
__device__ __align__(128) bf16 g_Xf1[TOT];
__device__ __align__(128) bf16 g_Xa1[TOT];
__device__ __align__(128) bf16 g_Xf2[TOT];
__device__ __align__(128) bf16 g_Xa2[TOT];
__device__ __align__(128) bf16 g_Xf1T[TOT];
__device__ __align__(128) bf16 g_Xa1T[TOT];
__device__ __align__(128) float g_res[TOT];
__device__ __align__(128) float g_res2[TOT];

// ---------------- prior row-normalization (single pass) ----------------
__global__ __launch_bounds__(256) void k_rownorm(const float* __restrict__ prior) {
    __shared__ float red[8];
    int row = blockIdx.x, t = threadIdx.x;
    const float* p = prior + (size_t)row * NP;
    float v[8];
    float s = 0.f;
#pragma unroll
    for (int u = 0; u < 8; u++) { v[u] = p[t + u * 256]; s += v[u]; }
#pragma unroll
    for (int o = 16; o; o >>= 1) s += __shfl_xor_sync(0xffffffffu, s, o);
    int warp = t >> 5, lane = t & 31;
    if (lane == 0) red[warp] = s;
    __syncthreads();
    if (t == 0) {
        float ss = 0.f;
#pragma unroll
        for (int i = 0; i < 8; i++) ss += red[i];
        red[0] = 1.0f / fmaxf(ss, 1e-12f);
    }
    __syncthreads();
    float inv = red[0];
    bf16* o = g_RfB + (size_t)row * NP;
#pragma unroll
    for (int u = 0; u < 8; u++) o[t + u * 256] = __float2bfloat16(v[u] * inv);
}

// ---------------- transposes ----------------
__global__ void k_transpose_f2b(const float* __restrict__ in, bf16* __restrict__ out,
                                int R, int Ccols) {
    __shared__ float tile[32][33];
    int bx = blockIdx.x * 32, by = blockIdx.y * 32;
    int tx = threadIdx.x, ty = threadIdx.y;   // 32 x 8
#pragma unroll
    for (int j = 0; j < 32; j += 8)
        tile[ty + j][tx] = in[(size_t)(by + ty + j) * Ccols + bx + tx];
    __syncthreads();
#pragma unroll
    for (int j = 0; j < 32; j += 8)
        out[(size_t)(bx + ty + j) * R + by + tx] = __float2bfloat16(tile[tx][ty + j]);
}

__global__ void k_transpose_b2b(const bf16* __restrict__ in, bf16* __restrict__ out,
                                int R, int Ccols) {
    __shared__ float tile[32][33];
    int bx = blockIdx.x * 32, by = blockIdx.y * 32;
    int tx = threadIdx.x, ty = threadIdx.y;
#pragma unroll
    for (int j = 0; j < 32; j += 8)
        tile[ty + j][tx] = __bfloat162float(in[(size_t)(by + ty + j) * Ccols + bx + tx]);
    __syncthreads();
#pragma unroll
    for (int j = 0; j < 32; j += 8)
        out[(size_t)(bx + ty + j) * R + by + tx] = __float2bfloat16(tile[tx][ty + j]);
}

// ---------------- mean pool over protein axis ----------------
__global__ void k_pool_f(const float* __restrict__ X) {
    int i = blockIdx.x, c = threadIdx.x;
    const float* p = X + (size_t)i * NCC + c;
    float s = 0.f;
#pragma unroll
    for (int k = 0; k < NC; k++) s += p[k * CDIM];
    g_pooled[i * CDIM + c] = s * (1.0f / NC);
}

__global__ void k_pool_b(const bf16* __restrict__ X) {
    int i = blockIdx.x, c = threadIdx.x;
    const bf16* p = X + (size_t)i * NCC + c;
    float s = 0.f;
#pragma unroll
    for (int k = 0; k < NC; k++) s += __bfloat162float(p[k * CDIM]);
    g_pooled[i * CDIM + c] = s * (1.0f / NC);
}

// ---------------- fused projections ----------------
#define PRJ_ROWS 16
#define PRJ_SMEM ((PRJ_ROWS*CDIM + 2*CDIM*65 + DDIM*65 + PRJ_ROWS*65) * 4)
__global__ __launch_bounds__(256) void k_proj(const float* __restrict__ W1,
                                              const float* __restrict__ W3,
                                              const float* __restrict__ W2) {
    extern __shared__ float ps[];
    float* pool_s = ps;
    float* w1s = pool_s + PRJ_ROWS * CDIM;
    float* w3s = w1s + CDIM * 65;
    float* w2s = w3s + CDIM * 65;
    float* e1s = w2s + DDIM * 65;

    int t = threadIdx.x;
    int r0 = blockIdx.x * PRJ_ROWS;

    for (int idx = t; idx < DDIM * CDIM; idx += 256) {
        int d = idx >> 7, c = idx & 127;
        w1s[c * 65 + d] = W1[idx];
        w3s[c * 65 + d] = W3[idx];
    }
    for (int idx = t; idx < DDIM * DDIM; idx += 256) {
        int d = idx >> 6, k = idx & 63;
        w2s[k * 65 + d] = W2[idx];
    }
    for (int idx = t; idx < PRJ_ROWS * CDIM; idx += 256)
        pool_s[idx] = g_pooled[r0 * CDIM + idx];
    __syncthreads();

    int d = t & 63, rg = t >> 6;
#pragma unroll
    for (int rr = 0; rr < 4; rr++) {
        int i = rg * 4 + rr;
        const float* pr = pool_s + i * CDIM;
        float s1 = 0.f, s3 = 0.f;
#pragma unroll 8
        for (int c = 0; c < CDIM; c++) {
            float pc = pr[c];
            s1 = fmaf(pc, w1s[c * 65 + d], s1);
            s3 = fmaf(pc, w3s[c * 65 + d], s3);
        }
        e1s[i * 65 + d] = s1;
        g_e3[(r0 + i) * DDIM + d] = s3;
    }
    __syncthreads();
#pragma unroll
    for (int rr = 0; rr < 4; rr++) {
        int i = rg * 4 + rr;
        const float* er = e1s + i * 65;
        float s = 0.f;
#pragma unroll 8
        for (int k = 0; k < DDIM; k++)
            s = fmaf(er[k], w2s[k * 65 + d], s);
        g_fm[(r0 + i) * DDIM + d] = s;
    }
}

// logits[i,n] = sum_k f[i,k]*e3[n,k]
__global__ __launch_bounds__(256) void k_logits() {
    __shared__ float Fs[64][65];
    __shared__ float Es[64][65];
    int bm = blockIdx.y * 64, bn = blockIdx.x * 64;
    int t = threadIdx.x;
    for (int idx = t; idx < 64 * 64; idx += 256) {
        int r = idx >> 6, c = idx & 63;
        Fs[r][c] = g_fm[(bm + r) * 64 + c];
        Es[r][c] = g_e3[(bn + r) * 64 + c];
    }
    __syncthreads();
    int tx = t & 15, ty = t >> 4;
    float acc[4][4] = {};
    for (int k = 0; k < 64; k++) {
        float a[4], b[4];
#pragma unroll
        for (int r = 0; r < 4; r++) { a[r] = Fs[ty * 4 + r][k]; b[r] = Es[tx * 4 + r][k]; }
#pragma unroll
        for (int i = 0; i < 4; i++)
#pragma unroll
            for (int j = 0; j < 4; j++) acc[i][j] += a[i] * b[j];
    }
#pragma unroll
    for (int i = 0; i < 4; i++)
#pragma unroll
        for (int j = 0; j < 4; j++)
            g_attn[(size_t)(bm + ty * 4 + i) * NP + bn + tx * 4 + j] = acc[i][j];
}

// ---------------- fused softmax + top-p bisection + mask, 1 barrier/reduction ------
__global__ __launch_bounds__(256) void k_softtopp() {
    __shared__ float red[2][8];
    int row = blockIdx.x, t = threadIdx.x;
    int warp = t >> 5, lane = t & 31;
    const float* a = g_attn + (size_t)row * NP;
    float v[8];
#pragma unroll
    for (int u = 0; u < 8; u++) v[u] = a[t + u * 256];

    int buf = 0;
    // block max (slot 0)
    float m = v[0];
#pragma unroll
    for (int u = 1; u < 8; u++) m = fmaxf(m, v[u]);
#pragma unroll
    for (int o = 16; o; o >>= 1) m = fmaxf(m, __shfl_xor_sync(0xffffffffu, m, o));
    if (lane == 0) red[buf][warp] = m;
    __syncthreads();
    {
        float mm = red[buf][0];
#pragma unroll
        for (int i = 1; i < 8; i++) mm = fmaxf(mm, red[buf][i]);
        m = mm;
    }
    buf ^= 1;

    // exp + total
    float e[8];
    float tot = 0.f;
#pragma unroll
    for (int u = 0; u < 8; u++) { e[u] = __expf(v[u] - m); tot += e[u]; }
#pragma unroll
    for (int o = 16; o; o >>= 1) tot += __shfl_xor_sync(0xffffffffu, tot, o);
    if (lane == 0) red[buf][warp] = tot;
    __syncthreads();
    {
        float s = 0.f;
#pragma unroll
        for (int i = 0; i < 8; i++) s += red[buf][i];
        tot = s;
    }
    buf ^= 1;

    float target = P_TOPP * tot;
    // bisection on positive-float bit patterns: largest thr with F(thr) >= target
    unsigned lo = 0u, hi = 0x3F800000u;
    while (lo < hi) {
        unsigned mid = lo + ((hi - lo + 1) >> 1);
        float tm = __uint_as_float(mid);
        float p = 0.f;
#pragma unroll
        for (int u = 0; u < 8; u++) p += (e[u] >= tm) ? e[u] : 0.f;
#pragma unroll
        for (int o = 16; o; o >>= 1) p += __shfl_xor_sync(0xffffffffu, p, o);
        if (lane == 0) red[buf][warp] = p;
        __syncthreads();
        {
            float s = 0.f;
#pragma unroll
            for (int i = 0; i < 8; i++) s += red[buf][i];
            p = s;
        }
        buf ^= 1;
        if (p >= target) lo = mid; else hi = mid - 1;
    }
    float thr = __uint_as_float(lo);

    float F = 0.f;
#pragma unroll
    for (int u = 0; u < 8; u++) F += (e[u] >= thr) ? e[u] : 0.f;
#pragma unroll
    for (int o = 16; o; o >>= 1) F += __shfl_xor_sync(0xffffffffu, F, o);
    if (lane == 0) red[buf][warp] = F;
    __syncthreads();
    {
        float s = 0.f;
#pragma unroll
        for (int i = 0; i < 8; i++) s += red[buf][i];
        F = s;
    }
    float inv = 1.0f / fmaxf(F, 1e-30f);
    bf16* o = g_attnB + (size_t)row * NP;
#pragma unroll
    for (int u = 0; u < 8; u++)
        o[t + u * 256] = __float2bfloat16((e[u] >= thr) ? e[u] * inv : 0.0f);
}

// ---------------- bf16 tensor-core GEMM: 128x128 tile, 4-stage ring (validated) -----
#define CP_ASYNC16(dst_u32, src_ptr) \
    asm volatile("cp.async.cg.shared.global [%0], [%1], 16;\n" :: "r"(dst_u32), "l"(src_ptr))
#define CP_COMMIT() asm volatile("cp.async.commit_group;\n" ::: "memory")
#define MMA16816(d, a, b) \
    asm volatile("mma.sync.aligned.m16n8k16.row.col.f32.bf16.bf16.f32 " \
                 "{%0,%1,%2,%3},{%4,%5,%6,%7},{%8,%9},{%0,%1,%2,%3};" \
                 : "+f"(d[0]), "+f"(d[1]), "+f"(d[2]), "+f"(d[3]) \
                 : "r"(a[0]), "r"(a[1]), "r"(a[2]), "r"(a[3]), "r"(b[0]), "r"(b[1]))
#define LDSM_X4(r0, r1, r2, r3, addr) \
    asm volatile("ldmatrix.sync.aligned.m8n8.x4.shared.b16 {%0,%1,%2,%3}, [%4];" \
                 : "=r"(r0), "=r"(r1), "=r"(r2), "=r"(r3) : "r"(addr))

#define GSTAGE_B 20480
#define G_SMEM   (4 * GSTAGE_B)

__global__ __launch_bounds__(256, 2) void k_gemm_bf16_dual(
    const bf16* __restrict__ A0, const bf16* __restrict__ BT0, bf16* __restrict__ C0,
    const bf16* __restrict__ A1, const bf16* __restrict__ BT1, bf16* __restrict__ C1,
    int M, int N, int K)
{
    const bf16* A  = blockIdx.z ? A1  : A0;
    const bf16* BT = blockIdx.z ? BT1 : BT0;
    bf16*       C  = blockIdx.z ? C1  : C0;

    extern __shared__ __align__(128) uint32_t sg[];
    uint32_t smBase = (uint32_t)__cvta_generic_to_shared(sg);
    int t = threadIdx.x;
    int bm = blockIdx.y << 7, bn = blockIdx.x << 7;
    int warp = t >> 5, lane = t & 31;
    int wm = warp & 3, wn = warp >> 2;
    int g = lane >> 2, tq = lane & 3;

    int lrow = t >> 2, lchunk = t & 3;
    const bf16* gA0 = A  + (size_t)(bm + lrow) * K      + lchunk * 8;
    const bf16* gA1 = A  + (size_t)(bm + lrow + 64) * K + lchunk * 8;
    const bf16* gB0 = BT + (size_t)(bn + lrow) * K      + lchunk * 8;
    const bf16* gB1 = BT + (size_t)(bn + lrow + 64) * K + lchunk * 8;
    uint32_t aD0 = smBase + ((lrow * 20 + lchunk * 4) << 2);
    uint32_t aD1 = smBase + (((lrow + 64) * 20 + lchunk * 4) << 2);
    uint32_t bD0 = smBase + ((2560 + lrow * 20 + lchunk * 4) << 2);
    uint32_t bD1 = smBase + ((2560 + (lrow + 64) * 20 + lchunk * 4) << 2);

    uint32_t aFrag = smBase + (((wm * 32 + (lane & 15)) * 20 + (lane >> 4) * 4) << 2);
    uint32_t bFrag = smBase + ((2560 + (wn * 64 + (lane & 15)) * 20 + (lane >> 4) * 4) << 2);

    float acc[2][8][4] = {};
    const int NT = K >> 5;

    auto load_tile = [&](int it, int stg) {
        size_t ko = (size_t)it << 5;
        uint32_t o = stg * GSTAGE_B;
        CP_ASYNC16(aD0 + o, gA0 + ko);
        CP_ASYNC16(aD1 + o, gA1 + ko);
        CP_ASYNC16(bD0 + o, gB0 + ko);
        CP_ASYNC16(bD1 + o, gB1 + ko);
        CP_COMMIT();
    };

    load_tile(0, 0);
    load_tile(1, 1);
    load_tile(2, 2);

    int stg = 0;
    for (int it = 0; it < NT; it++) {
        if (it <= NT - 3)      asm volatile("cp.async.wait_group 2;\n" ::: "memory");
        else if (it == NT - 2) asm volatile("cp.async.wait_group 1;\n" ::: "memory");
        else                   asm volatile("cp.async.wait_group 0;\n" ::: "memory");
        __syncthreads();
        if (it + 3 < NT) {
            int ps = stg + 3; if (ps >= 4) ps -= 4;
            load_tile(it + 3, ps);
        }

        uint32_t sOff = stg * GSTAGE_B;
#pragma unroll
        for (int s = 0; s < 2; s++) {
            uint32_t a[2][4], b[8][2];
#pragma unroll
            for (int mi = 0; mi < 2; mi++) {
                uint32_t ad = aFrag + sOff + ((mi * 16 * 20 + s * 8) << 2);
                LDSM_X4(a[mi][0], a[mi][1], a[mi][2], a[mi][3], ad);
            }
#pragma unroll
            for (int p = 0; p < 4; p++) {
                uint32_t bd = bFrag + sOff + ((p * 16 * 20 + s * 8) << 2);
                uint32_t r0, r1, r2, r3;
                LDSM_X4(r0, r1, r2, r3, bd);
                b[2 * p][0] = r0; b[2 * p + 1][0] = r1;
                b[2 * p][1] = r2; b[2 * p + 1][1] = r3;
            }
#pragma unroll
            for (int mi = 0; mi < 2; mi++)
#pragma unroll
                for (int ni = 0; ni < 8; ni++)
                    MMA16816(acc[mi][ni], a[mi], b[ni]);
        }
        stg++; if (stg == 4) stg = 0;
    }

#pragma unroll
    for (int mi = 0; mi < 2; mi++) {
#pragma unroll
        for (int ni = 0; ni < 8; ni++) {
            int row = bm + wm * 32 + mi * 16 + g;
            int col = bn + wn * 64 + ni * 8 + tq * 2;
            __nv_bfloat162* p0 = (__nv_bfloat162*)&C[(size_t)row * N + col];
            __nv_bfloat162* p1 = (__nv_bfloat162*)&C[(size_t)(row + 8) * N + col];
            *p0 = __float22bfloat162_rn(make_float2(acc[mi][ni][0], acc[mi][ni][1]));
            *p1 = __float22bfloat162_rn(make_float2(acc[mi][ni][2], acc[mi][ni][3]));
        }
    }
}

// ---------------- tensor-core delta: R = Xf@Pw^T + Xa@Aw^T (write-only) ------------
__global__ __launch_bounds__(256) void k_delta_mma(
    const bf16* __restrict__ Xf, const bf16* __restrict__ Xa,
    const float* __restrict__ Pw, const float* __restrict__ Aw,
    float* __restrict__ R)
{
    extern __shared__ uint32_t sm[];
    uint32_t* sPw = sm;
    uint32_t* sAw = sm + 10240;
    uint32_t* sXf = sm + 20480;
    uint32_t* sXa = sm + 30720;
    int t = threadIdx.x;
    size_t r0 = (size_t)blockIdx.x * 128;

    for (int idx = t; idx < 128 * 64; idx += 256) {
        int n = idx >> 6, w = idx & 63;
        int c = w >> 4, ww = w & 15;
        float2 pv = *(const float2*)&Pw[n * 128 + w * 2];
        float2 av = *(const float2*)&Aw[n * 128 + w * 2];
        __nv_bfloat162 pb = __float22bfloat162_rn(pv);
        __nv_bfloat162 ab = __float22bfloat162_rn(av);
        sPw[c * 2560 + n * 20 + ww] = *(uint32_t*)&pb;
        sAw[c * 2560 + n * 20 + ww] = *(uint32_t*)&ab;
    }
    const uint32_t* xf32 = (const uint32_t*)(Xf + r0 * 128);
    const uint32_t* xa32 = (const uint32_t*)(Xa + r0 * 128);
    for (int idx = t; idx < 128 * 64; idx += 256) {
        int n = idx >> 6, w = idx & 63;
        int c = w >> 4, ww = w & 15;
        sXf[c * 2560 + n * 20 + ww] = xf32[n * 64 + w];
        sXa[c * 2560 + n * 20 + ww] = xa32[n * 64 + w];
    }
    __syncthreads();

    int warp = t >> 5, lane = t & 31;
    int wm = warp & 3, wn = warp >> 2;
    int g = lane >> 2, tq = lane & 3;
    float acc[2][8][4] = {};

#pragma unroll
    for (int c = 0; c < 4; c++) {
        const uint32_t* cf = sXf + c * 2560;
        const uint32_t* ca = sXa + c * 2560;
        const uint32_t* cp = sPw + c * 2560;
        const uint32_t* cw = sAw + c * 2560;
#pragma unroll
        for (int s = 0; s < 2; s++) {
            uint32_t af[2][4], aa[2][4], bp[8][2], ba[8][2];
#pragma unroll
            for (int mi = 0; mi < 2; mi++) {
                int r = (wm * 32 + mi * 16 + g) * 20 + s * 8 + tq;
                af[mi][0] = cf[r];       af[mi][1] = cf[r + 160];
                af[mi][2] = cf[r + 4];   af[mi][3] = cf[r + 164];
                aa[mi][0] = ca[r];       aa[mi][1] = ca[r + 160];
                aa[mi][2] = ca[r + 4];   aa[mi][3] = ca[r + 164];
            }
#pragma unroll
            for (int ni = 0; ni < 8; ni++) {
                int rb = (wn * 64 + ni * 8 + g) * 20 + s * 8 + tq;
                bp[ni][0] = cp[rb]; bp[ni][1] = cp[rb + 4];
                ba[ni][0] = cw[rb]; ba[ni][1] = cw[rb + 4];
            }
#pragma unroll
            for (int mi = 0; mi < 2; mi++)
#pragma unroll
                for (int ni = 0; ni < 8; ni++) {
                    MMA16816(acc[mi][ni], af[mi], bp[ni]);
                    MMA16816(acc[mi][ni], aa[mi], ba[ni]);
                }
        }
    }

#pragma unroll
    for (int mi = 0; mi < 2; mi++) {
#pragma unroll
        for (int ni = 0; ni < 8; ni++) {
            int row = wm * 32 + mi * 16 + g;
            int col = wn * 64 + ni * 8 + tq * 2;
            float* p0 = &R[(r0 + row) * 128 + col];
            float* p1 = &R[(r0 + row + 8) * 128 + col];
            *(float2*)p0 = make_float2(acc[mi][ni][0], acc[mi][ni][1]);
            *(float2*)p1 = make_float2(acc[mi][ni][2], acc[mi][ni][3]);
        }
    }
}

// ---------------- final: out = LN(x + sigmoid(alpha)*(res+res2)) ----------------
__global__ void k_ln(const float* __restrict__ x, const float* __restrict__ gamma,
                     const float* __restrict__ beta, const float* __restrict__ alpha,
                     float* __restrict__ out) {
    int row = blockIdx.x * 8 + (threadIdx.x >> 5);
    int lane = threadIdx.x & 31;
    float gate = 1.0f / (1.0f + expf(-alpha[0]));
    size_t base = (size_t)row * CDIM;
    float h[4];
    float s = 0.f;
#pragma unroll
    for (int u = 0; u < 4; u++) {
        int c = lane + u * 32;
        h[u] = x[base + c] + gate * (g_res[base + c] + g_res2[base + c]);
        s += h[u];
    }
#pragma unroll
    for (int o = 16; o; o >>= 1) s += __shfl_xor_sync(0xffffffffu, s, o);
    float mu = s * (1.0f / CDIM);
    float v = 0.f;
#pragma unroll
    for (int u = 0; u < 4; u++) { float d = h[u] - mu; v += d * d; }
#pragma unroll
    for (int o = 16; o; o >>= 1) v += __shfl_xor_sync(0xffffffffu, v, o);
    float rs = rsqrtf(v * (1.0f / CDIM) + LN_EPS);
#pragma unroll
    for (int u = 0; u < 4; u++) {
        int c = lane + u * 32;
        out[base + c] = (h[u] - mu) * rs * gamma[c] + beta[c];
    }
}

// ---------------- host orchestration ----------------
extern "C" void kernel_launch(void* const* d_in, const int* in_sizes, int n_in,
                              void* d_out, int out_size) {
    const float* x     = (const float*)d_in[0];
    const float* prior = (const float*)d_in[1];
    const float* W1    = (const float*)d_in[2];
    const float* W2    = (const float*)d_in[3];
    const float* W3    = (const float*)d_in[4];
    const float* Pfw   = (const float*)d_in[5];
    const float* Awt   = (const float*)d_in[6];
    const float* gamma = (const float*)d_in[7];
    const float* beta  = (const float*)d_in[8];
    const float* alpha = (const float*)d_in[9];
    float* out = (float*)d_out;

    bf16 *RfB, *attnB, *xT, *Xf1, *Xa1, *Xf2, *Xa2, *Xf1T, *Xa1T;
    float *res, *res2;
    cudaGetSymbolAddress((void**)&RfB,   g_RfB);
    cudaGetSymbolAddress((void**)&attnB, g_attnB);
    cudaGetSymbolAddress((void**)&xT,    g_xT);
    cudaGetSymbolAddress((void**)&Xf1,   g_Xf1);
    cudaGetSymbolAddress((void**)&Xa1,   g_Xa1);
    cudaGetSymbolAddress((void**)&Xf2,   g_Xf2);
    cudaGetSymbolAddress((void**)&Xa2,   g_Xa2);
    cudaGetSymbolAddress((void**)&Xf1T,  g_Xf1T);
    cudaGetSymbolAddress((void**)&Xa1T,  g_Xa1T);
    cudaGetSymbolAddress((void**)&res,   g_res);
    cudaGetSymbolAddress((void**)&res2,  g_res2);

    static bool attr_done = false;
    if (!attr_done) {
        cudaFuncSetAttribute(k_delta_mma, cudaFuncAttributeMaxDynamicSharedMemorySize, 163840);
        cudaFuncSetAttribute(k_gemm_bf16_dual, cudaFuncAttributeMaxDynamicSharedMemorySize, G_SMEM);
        cudaFuncSetAttribute(k_proj, cudaFuncAttributeMaxDynamicSharedMemorySize, PRJ_SMEM);
        attr_done = true;
    }

    k_rownorm<<<NP, 256>>>(prior);
    k_transpose_f2b<<<dim3(NCC / 32, NP / 32), dim3(32, 8)>>>(x, xT, NP, NCC);

    for (int step = 0; step < 2; step++) {
        if (step == 0) k_pool_f<<<NP, CDIM>>>(x);
        else           k_pool_b<<<NP, CDIM>>>(Xa1);
        k_proj<<<NP / PRJ_ROWS, 256, PRJ_SMEM>>>(W1, W3, W2);
        k_logits<<<dim3(32, 32), 256>>>();
        k_softtopp<<<NP, 256>>>();

        const bf16* BT_f = step ? (const bf16*)Xf1T : (const bf16*)xT;
        const bf16* BT_a = step ? (const bf16*)Xa1T : (const bf16*)xT;
        bf16* Xf_out = step ? Xf2 : Xf1;
        bf16* Xa_out = step ? Xa2 : Xa1;

        k_gemm_bf16_dual<<<dim3(NCC / 128, NP / 128, 2), 256, G_SMEM>>>(
            RfB, BT_f, Xf_out, attnB, BT_a, Xa_out, NP, NCC, NP);

        k_delta_mma<<<1024, 256, 163840>>>(Xf_out, Xa_out,
                               Pfw + (size_t)step * CDIM * CDIM,
                               Awt + (size_t)step * CDIM * CDIM,
                               step ? res2 : res);

        if (step == 0) {
            k_transpose_b2b<<<dim3(NCC / 32, NP / 32), dim3(32, 8)>>>(Xf1, Xf1T, NP, NCC);
            k_transpose_b2b<<<dim3(NCC / 32, NP / 32), dim3(32, 8)>>>(Xa1, Xa1T, NP, NCC);
        }
    }

    k_ln<<<(int)(TOT / CDIM / 8), 256>>>(x, gamma, beta, alpha, out);
}

// round 16
// speedup vs baseline: 1.0050x; 1.0050x over previous
#include <cuda_runtime.h>
#include <cuda_bf16.h>
#include <cstdint>

#define NP 2048
#define NC 64
#define CDIM 128
#define DDIM 64
#define NCC (NC*CDIM)              /* 8192 */
#define TOT ((size_t)NP*NCC)       /* 16777216 */
#define P_TOPP 0.9f
#define LN_EPS 1e-5f

typedef __nv_bfloat16 bf16;

// ---------------- scratch (device globals; allowed) ----------------
__device__ __align__(128) bf16  g_RfB[(size_t)NP*NP];
__device__ __align__(128) float g_attn[(size_t)NP*NP];     // raw logits
__device__ __align__(128) bf16  g_attnB[(size_t)NP*NP];    // masked+renormed bf16
__device__ float g_pooled[NP*CDIM];
__device__ float g_e3[NP*DDIM];
__device__ float g_fm[NP*DDIM];
__device__ __align__(128) bf16 g_xT[TOT];
__device__ __align__(128) bf16 g_Xf1[TOT];
__device__ __align__(128) bf16 g_Xa1[TOT];
__device__ __align__(128) bf16 g_Xf2[TOT];
__device__ __align__(128) bf16 g_Xa2[TOT];
__device__ __align__(128) bf16 g_Xf1T[TOT];
__device__ __align__(128) bf16 g_Xa1T[TOT];
__device__ __align__(128) float g_res[TOT];
__device__ __align__(128) float g_res2[TOT];

// ---------------- prior row-normalization (single pass) ----------------
__global__ __launch_bounds__(256) void k_rownorm(const float* __restrict__ prior) {
    __shared__ float red[8];
    int row = blockIdx.x, t = threadIdx.x;
    const float* p = prior + (size_t)row * NP;
    float v[8];
    float s = 0.f;
#pragma unroll
    for (int u = 0; u < 8; u++) { v[u] = p[t + u * 256]; s += v[u]; }
#pragma unroll
    for (int o = 16; o; o >>= 1) s += __shfl_xor_sync(0xffffffffu, s, o);
    int warp = t >> 5, lane = t & 31;
    if (lane == 0) red[warp] = s;
    __syncthreads();
    if (t == 0) {
        float ss = 0.f;
#pragma unroll
        for (int i = 0; i < 8; i++) ss += red[i];
        red[0] = 1.0f / fmaxf(ss, 1e-12f);
    }
    __syncthreads();
    float inv = red[0];
    bf16* o = g_RfB + (size_t)row * NP;
#pragma unroll
    for (int u = 0; u < 8; u++) o[t + u * 256] = __float2bfloat16(v[u] * inv);
}

// ---------------- transposes ----------------
__global__ void k_transpose_f2b(const float* __restrict__ in, bf16* __restrict__ out,
                                int R, int Ccols) {
    __shared__ float tile[32][33];
    int bx = blockIdx.x * 32, by = blockIdx.y * 32;
    int tx = threadIdx.x, ty = threadIdx.y;   // 32 x 8
#pragma unroll
    for (int j = 0; j < 32; j += 8)
        tile[ty + j][tx] = in[(size_t)(by + ty + j) * Ccols + bx + tx];
    __syncthreads();
#pragma unroll
    for (int j = 0; j < 32; j += 8)
        out[(size_t)(bx + ty + j) * R + by + tx] = __float2bfloat16(tile[tx][ty + j]);
}

__global__ void k_transpose_b2b(const bf16* __restrict__ in, bf16* __restrict__ out,
                                int R, int Ccols) {
    __shared__ float tile[32][33];
    int bx = blockIdx.x * 32, by = blockIdx.y * 32;
    int tx = threadIdx.x, ty = threadIdx.y;
#pragma unroll
    for (int j = 0; j < 32; j += 8)
        tile[ty + j][tx] = __bfloat162float(in[(size_t)(by + ty + j) * Ccols + bx + tx]);
    __syncthreads();
#pragma unroll
    for (int j = 0; j < 32; j += 8)
        out[(size_t)(bx + ty + j) * R + by + tx] = __float2bfloat16(tile[tx][ty + j]);
}

// ---------------- mean pool over protein axis ----------------
__global__ void k_pool_f(const float* __restrict__ X) {
    int i = blockIdx.x, c = threadIdx.x;
    const float* p = X + (size_t)i * NCC + c;
    float s = 0.f;
#pragma unroll
    for (int k = 0; k < NC; k++) s += p[k * CDIM];
    g_pooled[i * CDIM + c] = s * (1.0f / NC);
}

__global__ void k_pool_b(const bf16* __restrict__ X) {
    int i = blockIdx.x, c = threadIdx.x;
    const bf16* p = X + (size_t)i * NCC + c;
    float s = 0.f;
#pragma unroll
    for (int k = 0; k < NC; k++) s += __bfloat162float(p[k * CDIM]);
    g_pooled[i * CDIM + c] = s * (1.0f / NC);
}

// ---------------- fused projections ----------------
#define PRJ_ROWS 16
#define PRJ_SMEM ((PRJ_ROWS*CDIM + 2*CDIM*65 + DDIM*65 + PRJ_ROWS*65) * 4)
__global__ __launch_bounds__(256) void k_proj(const float* __restrict__ W1,
                                              const float* __restrict__ W3,
                                              const float* __restrict__ W2) {
    extern __shared__ float ps[];
    float* pool_s = ps;
    float* w1s = pool_s + PRJ_ROWS * CDIM;
    float* w3s = w1s + CDIM * 65;
    float* w2s = w3s + CDIM * 65;
    float* e1s = w2s + DDIM * 65;

    int t = threadIdx.x;
    int r0 = blockIdx.x * PRJ_ROWS;

    for (int idx = t; idx < DDIM * CDIM; idx += 256) {
        int d = idx >> 7, c = idx & 127;
        w1s[c * 65 + d] = W1[idx];
        w3s[c * 65 + d] = W3[idx];
    }
    for (int idx = t; idx < DDIM * DDIM; idx += 256) {
        int d = idx >> 6, k = idx & 63;
        w2s[k * 65 + d] = W2[idx];
    }
    for (int idx = t; idx < PRJ_ROWS * CDIM; idx += 256)
        pool_s[idx] = g_pooled[r0 * CDIM + idx];
    __syncthreads();

    int d = t & 63, rg = t >> 6;
#pragma unroll
    for (int rr = 0; rr < 4; rr++) {
        int i = rg * 4 + rr;
        const float* pr = pool_s + i * CDIM;
        float s1 = 0.f, s3 = 0.f;
#pragma unroll 8
        for (int c = 0; c < CDIM; c++) {
            float pc = pr[c];
            s1 = fmaf(pc, w1s[c * 65 + d], s1);
            s3 = fmaf(pc, w3s[c * 65 + d], s3);
        }
        e1s[i * 65 + d] = s1;
        g_e3[(r0 + i) * DDIM + d] = s3;
    }
    __syncthreads();
#pragma unroll
    for (int rr = 0; rr < 4; rr++) {
        int i = rg * 4 + rr;
        const float* er = e1s + i * 65;
        float s = 0.f;
#pragma unroll 8
        for (int k = 0; k < DDIM; k++)
            s = fmaf(er[k], w2s[k * 65 + d], s);
        g_fm[(r0 + i) * DDIM + d] = s;
    }
}

// logits[i,n] = sum_k f[i,k]*e3[n,k]
__global__ __launch_bounds__(256) void k_logits() {
    __shared__ float Fs[64][65];
    __shared__ float Es[64][65];
    int bm = blockIdx.y * 64, bn = blockIdx.x * 64;
    int t = threadIdx.x;
    for (int idx = t; idx < 64 * 64; idx += 256) {
        int r = idx >> 6, c = idx & 63;
        Fs[r][c] = g_fm[(bm + r) * 64 + c];
        Es[r][c] = g_e3[(bn + r) * 64 + c];
    }
    __syncthreads();
    int tx = t & 15, ty = t >> 4;
    float acc[4][4] = {};
    for (int k = 0; k < 64; k++) {
        float a[4], b[4];
#pragma unroll
        for (int r = 0; r < 4; r++) { a[r] = Fs[ty * 4 + r][k]; b[r] = Es[tx * 4 + r][k]; }
#pragma unroll
        for (int i = 0; i < 4; i++)
#pragma unroll
            for (int j = 0; j < 4; j++) acc[i][j] += a[i] * b[j];
    }
#pragma unroll
    for (int i = 0; i < 4; i++)
#pragma unroll
        for (int j = 0; j < 4; j++)
            g_attn[(size_t)(bm + ty * 4 + i) * NP + bn + tx * 4 + j] = acc[i][j];
}

// ---------------- fused softmax + top-p bisection + mask, 1 barrier/reduction ------
__global__ __launch_bounds__(256) void k_softtopp() {
    __shared__ float red[2][8];
    int row = blockIdx.x, t = threadIdx.x;
    int warp = t >> 5, lane = t & 31;
    const float* a = g_attn + (size_t)row * NP;
    float v[8];
#pragma unroll
    for (int u = 0; u < 8; u++) v[u] = a[t + u * 256];

    int buf = 0;
    // block max (slot 0)
    float m = v[0];
#pragma unroll
    for (int u = 1; u < 8; u++) m = fmaxf(m, v[u]);
#pragma unroll
    for (int o = 16; o; o >>= 1) m = fmaxf(m, __shfl_xor_sync(0xffffffffu, m, o));
    if (lane == 0) red[buf][warp] = m;
    __syncthreads();
    {
        float mm = red[buf][0];
#pragma unroll
        for (int i = 1; i < 8; i++) mm = fmaxf(mm, red[buf][i]);
        m = mm;
    }
    buf ^= 1;

    // exp + total
    float e[8];
    float tot = 0.f;
#pragma unroll
    for (int u = 0; u < 8; u++) { e[u] = __expf(v[u] - m); tot += e[u]; }
#pragma unroll
    for (int o = 16; o; o >>= 1) tot += __shfl_xor_sync(0xffffffffu, tot, o);
    if (lane == 0) red[buf][warp] = tot;
    __syncthreads();
    {
        float s = 0.f;
#pragma unroll
        for (int i = 0; i < 8; i++) s += red[buf][i];
        tot = s;
    }
    buf ^= 1;

    float target = P_TOPP * tot;
    // bisection on positive-float bit patterns: largest thr with F(thr) >= target
    unsigned lo = 0u, hi = 0x3F800000u;
    while (lo < hi) {
        unsigned mid = lo + ((hi - lo + 1) >> 1);
        float tm = __uint_as_float(mid);
        float p = 0.f;
#pragma unroll
        for (int u = 0; u < 8; u++) p += (e[u] >= tm) ? e[u] : 0.f;
#pragma unroll
        for (int o = 16; o; o >>= 1) p += __shfl_xor_sync(0xffffffffu, p, o);
        if (lane == 0) red[buf][warp] = p;
        __syncthreads();
        {
            float s = 0.f;
#pragma unroll
            for (int i = 0; i < 8; i++) s += red[buf][i];
            p = s;
        }
        buf ^= 1;
        if (p >= target) lo = mid; else hi = mid - 1;
    }
    float thr = __uint_as_float(lo);

    float F = 0.f;
#pragma unroll
    for (int u = 0; u < 8; u++) F += (e[u] >= thr) ? e[u] : 0.f;
#pragma unroll
    for (int o = 16; o; o >>= 1) F += __shfl_xor_sync(0xffffffffu, F, o);
    if (lane == 0) red[buf][warp] = F;
    __syncthreads();
    {
        float s = 0.f;
#pragma unroll
        for (int i = 0; i < 8; i++) s += red[buf][i];
        F = s;
    }
    float inv = 1.0f / fmaxf(F, 1e-30f);
    bf16* o = g_attnB + (size_t)row * NP;
#pragma unroll
    for (int u = 0; u < 8; u++)
        o[t + u * 256] = __float2bfloat16((e[u] >= thr) ? e[u] * inv : 0.0f);
}

// ---------------- bf16 tensor-core GEMM: 128x128 tile, 4-stage ring (validated) -----
#define CP_ASYNC16(dst_u32, src_ptr) \
    asm volatile("cp.async.cg.shared.global [%0], [%1], 16;\n" :: "r"(dst_u32), "l"(src_ptr))
#define CP_COMMIT() asm volatile("cp.async.commit_group;\n" ::: "memory")
#define MMA16816(d, a, b) \
    asm volatile("mma.sync.aligned.m16n8k16.row.col.f32.bf16.bf16.f32 " \
                 "{%0,%1,%2,%3},{%4,%5,%6,%7},{%8,%9},{%0,%1,%2,%3};" \
                 : "+f"(d[0]), "+f"(d[1]), "+f"(d[2]), "+f"(d[3]) \
                 : "r"(a[0]), "r"(a[1]), "r"(a[2]), "r"(a[3]), "r"(b[0]), "r"(b[1]))
#define LDSM_X4(r0, r1, r2, r3, addr) \
    asm volatile("ldmatrix.sync.aligned.m8n8.x4.shared.b16 {%0,%1,%2,%3}, [%4];" \
                 : "=r"(r0), "=r"(r1), "=r"(r2), "=r"(r3) : "r"(addr))

#define GSTAGE_B 20480
#define G_SMEM   (4 * GSTAGE_B)

__global__ __launch_bounds__(256, 2) void k_gemm_bf16_dual(
    const bf16* __restrict__ A0, const bf16* __restrict__ BT0, bf16* __restrict__ C0,
    const bf16* __restrict__ A1, const bf16* __restrict__ BT1, bf16* __restrict__ C1,
    int M, int N, int K)
{
    const bf16* A  = blockIdx.z ? A1  : A0;
    const bf16* BT = blockIdx.z ? BT1 : BT0;
    bf16*       C  = blockIdx.z ? C1  : C0;

    extern __shared__ __align__(128) uint32_t sg[];
    uint32_t smBase = (uint32_t)__cvta_generic_to_shared(sg);
    int t = threadIdx.x;
    int bm = blockIdx.y << 7, bn = blockIdx.x << 7;
    int warp = t >> 5, lane = t & 31;
    int wm = warp & 3, wn = warp >> 2;
    int g = lane >> 2, tq = lane & 3;

    int lrow = t >> 2, lchunk = t & 3;
    const bf16* gA0 = A  + (size_t)(bm + lrow) * K      + lchunk * 8;
    const bf16* gA1 = A  + (size_t)(bm + lrow + 64) * K + lchunk * 8;
    const bf16* gB0 = BT + (size_t)(bn + lrow) * K      + lchunk * 8;
    const bf16* gB1 = BT + (size_t)(bn + lrow + 64) * K + lchunk * 8;
    uint32_t aD0 = smBase + ((lrow * 20 + lchunk * 4) << 2);
    uint32_t aD1 = smBase + (((lrow + 64) * 20 + lchunk * 4) << 2);
    uint32_t bD0 = smBase + ((2560 + lrow * 20 + lchunk * 4) << 2);
    uint32_t bD1 = smBase + ((2560 + (lrow + 64) * 20 + lchunk * 4) << 2);

    uint32_t aFrag = smBase + (((wm * 32 + (lane & 15)) * 20 + (lane >> 4) * 4) << 2);
    uint32_t bFrag = smBase + ((2560 + (wn * 64 + (lane & 15)) * 20 + (lane >> 4) * 4) << 2);

    float acc[2][8][4] = {};
    const int NT = K >> 5;

    auto load_tile = [&](int it, int stg) {
        size_t ko = (size_t)it << 5;
        uint32_t o = stg * GSTAGE_B;
        CP_ASYNC16(aD0 + o, gA0 + ko);
        CP_ASYNC16(aD1 + o, gA1 + ko);
        CP_ASYNC16(bD0 + o, gB0 + ko);
        CP_ASYNC16(bD1 + o, gB1 + ko);
        CP_COMMIT();
    };

    load_tile(0, 0);
    load_tile(1, 1);
    load_tile(2, 2);

    int stg = 0;
    for (int it = 0; it < NT; it++) {
        if (it <= NT - 3)      asm volatile("cp.async.wait_group 2;\n" ::: "memory");
        else if (it == NT - 2) asm volatile("cp.async.wait_group 1;\n" ::: "memory");
        else                   asm volatile("cp.async.wait_group 0;\n" ::: "memory");
        __syncthreads();
        if (it + 3 < NT) {
            int ps = stg + 3; if (ps >= 4) ps -= 4;
            load_tile(it + 3, ps);
        }

        uint32_t sOff = stg * GSTAGE_B;
#pragma unroll
        for (int s = 0; s < 2; s++) {
            uint32_t a[2][4], b[8][2];
#pragma unroll
            for (int mi = 0; mi < 2; mi++) {
                uint32_t ad = aFrag + sOff + ((mi * 16 * 20 + s * 8) << 2);
                LDSM_X4(a[mi][0], a[mi][1], a[mi][2], a[mi][3], ad);
            }
#pragma unroll
            for (int p = 0; p < 4; p++) {
                uint32_t bd = bFrag + sOff + ((p * 16 * 20 + s * 8) << 2);
                uint32_t r0, r1, r2, r3;
                LDSM_X4(r0, r1, r2, r3, bd);
                b[2 * p][0] = r0; b[2 * p + 1][0] = r1;
                b[2 * p][1] = r2; b[2 * p + 1][1] = r3;
            }
#pragma unroll
            for (int mi = 0; mi < 2; mi++)
#pragma unroll
                for (int ni = 0; ni < 8; ni++)
                    MMA16816(acc[mi][ni], a[mi], b[ni]);
        }
        stg++; if (stg == 4) stg = 0;
    }

#pragma unroll
    for (int mi = 0; mi < 2; mi++) {
#pragma unroll
        for (int ni = 0; ni < 8; ni++) {
            int row = bm + wm * 32 + mi * 16 + g;
            int col = bn + wn * 64 + ni * 8 + tq * 2;
            __nv_bfloat162* p0 = (__nv_bfloat162*)&C[(size_t)row * N + col];
            __nv_bfloat162* p1 = (__nv_bfloat162*)&C[(size_t)(row + 8) * N + col];
            *p0 = __float22bfloat162_rn(make_float2(acc[mi][ni][0], acc[mi][ni][1]));
            *p1 = __float22bfloat162_rn(make_float2(acc[mi][ni][2], acc[mi][ni][3]));
        }
    }
}

// ---------------- tensor-core delta: R = Xf@Pw^T + Xa@Aw^T (write-only) ------------
__global__ __launch_bounds__(256) void k_delta_mma(
    const bf16* __restrict__ Xf, const bf16* __restrict__ Xa,
    const float* __restrict__ Pw, const float* __restrict__ Aw,
    float* __restrict__ R)
{
    extern __shared__ uint32_t sm[];
    uint32_t* sPw = sm;
    uint32_t* sAw = sm + 10240;
    uint32_t* sXf = sm + 20480;
    uint32_t* sXa = sm + 30720;
    int t = threadIdx.x;
    size_t r0 = (size_t)blockIdx.x * 128;

    for (int idx = t; idx < 128 * 64; idx += 256) {
        int n = idx >> 6, w = idx & 63;
        int c = w >> 4, ww = w & 15;
        float2 pv = *(const float2*)&Pw[n * 128 + w * 2];
        float2 av = *(const float2*)&Aw[n * 128 + w * 2];
        __nv_bfloat162 pb = __float22bfloat162_rn(pv);
        __nv_bfloat162 ab = __float22bfloat162_rn(av);
        sPw[c * 2560 + n * 20 + ww] = *(uint32_t*)&pb;
        sAw[c * 2560 + n * 20 + ww] = *(uint32_t*)&ab;
    }
    const uint32_t* xf32 = (const uint32_t*)(Xf + r0 * 128);
    const uint32_t* xa32 = (const uint32_t*)(Xa + r0 * 128);
    for (int idx = t; idx < 128 * 64; idx += 256) {
        int n = idx >> 6, w = idx & 63;
        int c = w >> 4, ww = w & 15;
        sXf[c * 2560 + n * 20 + ww] = xf32[n * 64 + w];
        sXa[c * 2560 + n * 20 + ww] = xa32[n * 64 + w];
    }
    __syncthreads();

    int warp = t >> 5, lane = t & 31;
    int wm = warp & 3, wn = warp >> 2;
    int g = lane >> 2, tq = lane & 3;
    float acc[2][8][4] = {};

#pragma unroll
    for (int c = 0; c < 4; c++) {
        const uint32_t* cf = sXf + c * 2560;
        const uint32_t* ca = sXa + c * 2560;
        const uint32_t* cp = sPw + c * 2560;
        const uint32_t* cw = sAw + c * 2560;
#pragma unroll
        for (int s = 0; s < 2; s++) {
            uint32_t af[2][4], aa[2][4], bp[8][2], ba[8][2];
#pragma unroll
            for (int mi = 0; mi < 2; mi++) {
                int r = (wm * 32 + mi * 16 + g) * 20 + s * 8 + tq;
                af[mi][0] = cf[r];       af[mi][1] = cf[r + 160];
                af[mi][2] = cf[r + 4];   af[mi][3] = cf[r + 164];
                aa[mi][0] = ca[r];       aa[mi][1] = ca[r + 160];
                aa[mi][2] = ca[r + 4];   aa[mi][3] = ca[r + 164];
            }
#pragma unroll
            for (int ni = 0; ni < 8; ni++) {
                int rb = (wn * 64 + ni * 8 + g) * 20 + s * 8 + tq;
                bp[ni][0] = cp[rb]; bp[ni][1] = cp[rb + 4];
                ba[ni][0] = cw[rb]; ba[ni][1] = cw[rb + 4];
            }
#pragma unroll
            for (int mi = 0; mi < 2; mi++)
#pragma unroll
                for (int ni = 0; ni < 8; ni++) {
                    MMA16816(acc[mi][ni], af[mi], bp[ni]);
                    MMA16816(acc[mi][ni], aa[mi], ba[ni]);
                }
        }
    }

#pragma unroll
    for (int mi = 0; mi < 2; mi++) {
#pragma unroll
        for (int ni = 0; ni < 8; ni++) {
            int row = wm * 32 + mi * 16 + g;
            int col = wn * 64 + ni * 8 + tq * 2;
            float* p0 = &R[(r0 + row) * 128 + col];
            float* p1 = &R[(r0 + row + 8) * 128 + col];
            *(float2*)p0 = make_float2(acc[mi][ni][0], acc[mi][ni][1]);
            *(float2*)p1 = make_float2(acc[mi][ni][2], acc[mi][ni][3]);
        }
    }
}

// ---------------- final: out = LN(x + sigmoid(alpha)*(res+res2)) ----------------
__global__ void k_ln(const float* __restrict__ x, const float* __restrict__ gamma,
                     const float* __restrict__ beta, const float* __restrict__ alpha,
                     float* __restrict__ out) {
    int row = blockIdx.x * 8 + (threadIdx.x >> 5);
    int lane = threadIdx.x & 31;
    float gate = 1.0f / (1.0f + expf(-alpha[0]));
    size_t base = (size_t)row * CDIM;
    float h[4];
    float s = 0.f;
#pragma unroll
    for (int u = 0; u < 4; u++) {
        int c = lane + u * 32;
        h[u] = x[base + c] + gate * (g_res[base + c] + g_res2[base + c]);
        s += h[u];
    }
#pragma unroll
    for (int o = 16; o; o >>= 1) s += __shfl_xor_sync(0xffffffffu, s, o);
    float mu = s * (1.0f / CDIM);
    float v = 0.f;
#pragma unroll
    for (int u = 0; u < 4; u++) { float d = h[u] - mu; v += d * d; }
#pragma unroll
    for (int o = 16; o; o >>= 1) v += __shfl_xor_sync(0xffffffffu, v, o);
    float rs = rsqrtf(v * (1.0f / CDIM) + LN_EPS);
#pragma unroll
    for (int u = 0; u < 4; u++) {
        int c = lane + u * 32;
        out[base + c] = (h[u] - mu) * rs * gamma[c] + beta[c];
    }
}

// ---------------- host orchestration ----------------
extern "C" void kernel_launch(void* const* d_in, const int* in_sizes, int n_in,
                              void* d_out, int out_size) {
    const float* x     = (const float*)d_in[0];
    const float* prior = (const float*)d_in[1];
    const float* W1    = (const float*)d_in[2];
    const float* W2    = (const float*)d_in[3];
    const float* W3    = (const float*)d_in[4];
    const float* Pfw   = (const float*)d_in[5];
    const float* Awt   = (const float*)d_in[6];
    const float* gamma = (const float*)d_in[7];
    const float* beta  = (const float*)d_in[8];
    const float* alpha = (const float*)d_in[9];
    float* out = (float*)d_out;

    bf16 *RfB, *attnB, *xT, *Xf1, *Xa1, *Xf2, *Xa2, *Xf1T, *Xa1T;
    float *res, *res2;
    cudaGetSymbolAddress((void**)&RfB,   g_RfB);
    cudaGetSymbolAddress((void**)&attnB, g_attnB);
    cudaGetSymbolAddress((void**)&xT,    g_xT);
    cudaGetSymbolAddress((void**)&Xf1,   g_Xf1);
    cudaGetSymbolAddress((void**)&Xa1,   g_Xa1);
    cudaGetSymbolAddress((void**)&Xf2,   g_Xf2);
    cudaGetSymbolAddress((void**)&Xa2,   g_Xa2);
    cudaGetSymbolAddress((void**)&Xf1T,  g_Xf1T);
    cudaGetSymbolAddress((void**)&Xa1T,  g_Xa1T);
    cudaGetSymbolAddress((void**)&res,   g_res);
    cudaGetSymbolAddress((void**)&res2,  g_res2);

    static bool attr_done = false;
    if (!attr_done) {
        cudaFuncSetAttribute(k_delta_mma, cudaFuncAttributeMaxDynamicSharedMemorySize, 163840);
        cudaFuncSetAttribute(k_gemm_bf16_dual, cudaFuncAttributeMaxDynamicSharedMemorySize, G_SMEM);
        cudaFuncSetAttribute(k_proj, cudaFuncAttributeMaxDynamicSharedMemorySize, PRJ_SMEM);
        attr_done = true;
    }

    k_rownorm<<<NP, 256>>>(prior);
    k_transpose_f2b<<<dim3(NCC / 32, NP / 32), dim3(32, 8)>>>(x, xT, NP, NCC);

    for (int step = 0; step < 2; step++) {
        if (step == 0) k_pool_f<<<NP, CDIM>>>(x);
        else           k_pool_b<<<NP, CDIM>>>(Xa1);
        k_proj<<<NP / PRJ_ROWS, 256, PRJ_SMEM>>>(W1, W3, W2);
        k_logits<<<dim3(32, 32), 256>>>();
        k_softtopp<<<NP, 256>>>();

        const bf16* BT_f = step ? (const bf16*)Xf1T : (const bf16*)xT;
        const bf16* BT_a = step ? (const bf16*)Xa1T : (const bf16*)xT;
        bf16* Xf_out = step ? Xf2 : Xf1;
        bf16* Xa_out = step ? Xa2 : Xa1;

        k_gemm_bf16_dual<<<dim3(NCC / 128, NP / 128, 2), 256, G_SMEM>>>(
            RfB, BT_f, Xf_out, attnB, BT_a, Xa_out, NP, NCC, NP);

        k_delta_mma<<<1024, 256, 163840>>>(Xf_out, Xa_out,
                               Pfw + (size_t)step * CDIM * CDIM,
                               Awt + (size_t)step * CDIM * CDIM,
                               step ? res2 : res);

        if (step == 0) {
            k_transpose_b2b<<<dim3(NCC / 32, NP / 32), dim3(32, 8)>>>(Xf1, Xf1T, NP, NCC);
            k_transpose_b2b<<<dim3(NCC / 32, NP / 32), dim3(32, 8)>>>(Xa1, Xa1T, NP, NCC);
        }
    }

    k_ln<<<(int)(TOT / CDIM / 8), 256>>>(x, gamma, beta, alpha, out);
}